// round 15
// baseline (speedup 1.0000x reference)
#include <cuda_runtime.h>

#define B_TOT 8192
#define N_NET 722
#define CAMD  10
#define IND   11
#define HD    10
#define LODD  6
#define GN    4     // nets per block (n uniform PER WARP -> weight broadcast kept)
#define ROWS  128   // batch rows per block

using u64 = unsigned long long;

static __device__ __forceinline__ u64 pk2(float a, float b) {
    u64 r; asm("mov.b64 %0, {%1, %2};" : "=l"(r) : "f"(a), "f"(b)); return r;
}
static __device__ __forceinline__ void unpk2(u64 v, float& a, float& b) {
    asm("mov.b64 {%0, %1}, %2;" : "=f"(a), "=f"(b) : "l"(v));
}
// Packed 2-wide fp32 FMA (Blackwell FFMA2) — only reachable via PTX.
static __device__ __forceinline__ u64 ffma2(u64 a, u64 b, u64 c) {
    u64 d; asm("fma.rn.f32x2 %0, %1, %2, %3;" : "=l"(d) : "l"(a), "l"(b), "l"(c)); return d;
}
static __device__ __forceinline__ u64 relu2(u64 v) {
    float a, b; unpk2(v, a, b);
    a = fmaxf(a, 0.0f); b = fmaxf(b, 0.0f);
    return pk2(a, b);
}
// 16-byte broadcast shared load: two duplicated weights -> feeds two FFMA2s.
static __device__ __forceinline__ void lds2(const u64* p, u64& w0, u64& w1) {
    asm("ld.shared.v2.u64 {%0, %1}, [%2];"
        : "=l"(w0), "=l"(w1) : "l"(__cvta_generic_to_shared(p)));
}
// 16-byte shared load of 4 floats.
static __device__ __forceinline__ float4 lds4f(const float* p) {
    float4 v;
    asm("ld.shared.v4.f32 {%0, %1, %2, %3}, [%4];"
        : "=f"(v.x), "=f"(v.y), "=f"(v.z), "=f"(v.w)
        : "l"(__cvta_generic_to_shared(p)));
    return v;
}

// R13 structure (best: 166.3us) with the camera path staged through smem,
// done correctly this time (R10's version used scattered per-element LDG):
//  1) block's 5120B camera slab staged with 320 fully-coalesced float4 LDGs
//     (~5 wf/warp amortized, replacing 100 wf/warp of strided LDG.128),
//  2) each thread reads its 80B (rows r0, r0+1) back as 5 conflict-free
//     LDS.128 (lane stride 20 words, gcd(20,32)=4 -> 8-lane phases tile all
//     32 banks exactly once) = 20 wf/warp inherent minimum,
//  3) identical register repack as R13; no extra __syncthreads (joins the
//     existing staging barrier).
__global__ __launch_bounds__(256, 3) void mlp_kernel(
    const float* __restrict__ prior,  // [B, N]
    const float* __restrict__ cam,    // [B, CAM]
    const float* __restrict__ W1,     // [N, IN, H]
    const float* __restrict__ b1,     // [N, H]
    const float* __restrict__ W2,     // [N, H, H]
    const float* __restrict__ b2,     // [N, H]
    const float* __restrict__ W3,     // [N, H, LOD]
    const float* __restrict__ b3,     // [N, LOD]
    float* __restrict__ out)          // [B, N, LOD]
{
    __shared__ __align__(16) u64 s_w1[GN][IND * HD];
    __shared__ __align__(16) u64 s_b1[GN][HD];
    __shared__ __align__(16) u64 s_w2[GN][HD * HD];
    __shared__ __align__(16) u64 s_b2[GN][HD];
    __shared__ __align__(16) u64 s_w3[GN][HD * LODD];
    __shared__ __align__(16) u64 s_b3[GN][LODD + 2];
    __shared__ float s_pr[ROWS][GN + 1];          // prior stage
    __shared__ float s_out[ROWS * 25];            // row stride 25 words (24 used)
    __shared__ __align__(16) float s_cam[ROWS * CAMD];  // raw camera slab, 5120B

    const int tid   = threadIdx.x;
    const int nbase = blockIdx.x * GN;
    const int bbase = blockIdx.y * ROWS;

    // ---- Stage 4 nets' weights, duplicated (w,w) ----
    for (int idx = tid; idx < GN * IND * HD; idx += 256) {
        int j = idx / (IND * HD), i = idx - j * (IND * HD);
        int nj = min(nbase + j, N_NET - 1);
        float v = W1[nj * IND * HD + i]; s_w1[j][i] = pk2(v, v);
    }
    for (int idx = tid; idx < GN * HD * HD; idx += 256) {
        int j = idx / (HD * HD), i = idx - j * (HD * HD);
        int nj = min(nbase + j, N_NET - 1);
        float v = W2[nj * HD * HD + i]; s_w2[j][i] = pk2(v, v);
    }
    for (int idx = tid; idx < GN * HD * LODD; idx += 256) {
        int j = idx / (HD * LODD), i = idx - j * (HD * LODD);
        int nj = min(nbase + j, N_NET - 1);
        float v = W3[nj * HD * LODD + i]; s_w3[j][i] = pk2(v, v);
    }
    if (tid < GN * HD) {
        int j = tid / HD, i = tid - j * HD;
        int nj = min(nbase + j, N_NET - 1);
        float v = b1[nj * HD + i]; s_b1[j][i] = pk2(v, v);
        v       = b2[nj * HD + i]; s_b2[j][i] = pk2(v, v);
    }
    if (tid < GN * LODD) {
        int j = tid / LODD, i = tid - j * LODD;
        int nj = min(nbase + j, N_NET - 1);
        float v = b3[nj * LODD + i]; s_b3[j][i] = pk2(v, v);
    }

    // ---- Stage prior[bbase..+127][nbase..+3] (coalesced 16B per row) ----
    for (int idx = tid; idx < ROWS * GN; idx += 256) {
        int r = idx >> 2, nt = idx & 3;
        int nj = min(nbase + nt, N_NET - 1);
        s_pr[r][nt] = prior[(size_t)(bbase + r) * N_NET + nj];
    }

    // ---- Stage camera slab: 1280 floats = 320 float4, fully coalesced ----
    {
        const float4* src = reinterpret_cast<const float4*>(cam + (size_t)bbase * CAMD);
        float4* dst = reinterpret_cast<float4*>(s_cam);
        dst[tid] = src[tid];                       // 256 float4
        if (tid < 64) dst[256 + tid] = src[256 + tid];  // remaining 64
    }
    __syncthreads();

    const int w  = tid >> 5;
    const int L  = tid & 31;
    const int ns = w & (GN - 1);   // net uniform per warp -> broadcast LDS
    const int rg = w >> 2;         // row group (2 per net)
    const int r0 = rg * 64 + L * 2;    // adjacent row pair (R11/R13 mapping)
    const int b0 = bbase + r0;

    // ---- Inputs: rows (r0, r0+1) = 80B contiguous in s_cam -> 5 LDS.128 ----
    // byte offset r0*40, r0 even -> 16B aligned; conflict-free (see header).
    u64 x[IND];
    x[0] = pk2(s_pr[r0][ns], s_pr[r0 + 1][ns]);
    {
        const float* base = s_cam + r0 * CAMD;
        float4 v0 = lds4f(base);
        float4 v1 = lds4f(base + 4);
        float4 v2 = lds4f(base + 8);
        float4 v3 = lds4f(base + 12);
        float4 v4 = lds4f(base + 16);
        // rowA = [v0.x..v1.w, v2.x, v2.y], rowB = [v2.z, v2.w, v3.x..v4.w]
        x[1]  = pk2(v0.x, v2.z);
        x[2]  = pk2(v0.y, v2.w);
        x[3]  = pk2(v0.z, v3.x);
        x[4]  = pk2(v0.w, v3.y);
        x[5]  = pk2(v1.x, v3.z);
        x[6]  = pk2(v1.y, v3.w);
        x[7]  = pk2(v1.z, v4.x);
        x[8]  = pk2(v1.w, v4.y);
        x[9]  = pk2(v2.x, v4.z);
        x[10] = pk2(v2.y, v4.w);
    }

    // ---- Layer 1: [IN=11] -> [H=10], ReLU ----
    u64 h1[HD];
#pragma unroll
    for (int h = 0; h < HD; h += 2) lds2(&s_b1[ns][h], h1[h], h1[h + 1]);
#pragma unroll
    for (int i = 0; i < IND; i++) {
#pragma unroll
        for (int h = 0; h < HD; h += 2) {
            u64 w0, w1v; lds2(&s_w1[ns][i * HD + h], w0, w1v);
            h1[h]     = ffma2(x[i], w0,  h1[h]);
            h1[h + 1] = ffma2(x[i], w1v, h1[h + 1]);
        }
    }
#pragma unroll
    for (int h = 0; h < HD; h++) h1[h] = relu2(h1[h]);

    // ---- Layer 2: [H=10] -> [H=10], ReLU ----
    u64 h2[HD];
#pragma unroll
    for (int k = 0; k < HD; k += 2) lds2(&s_b2[ns][k], h2[k], h2[k + 1]);
#pragma unroll
    for (int h = 0; h < HD; h++) {
#pragma unroll
        for (int k = 0; k < HD; k += 2) {
            u64 w0, w1v; lds2(&s_w2[ns][h * HD + k], w0, w1v);
            h2[k]     = ffma2(h1[h], w0,  h2[k]);
            h2[k + 1] = ffma2(h1[h], w1v, h2[k + 1]);
        }
    }
#pragma unroll
    for (int k = 0; k < HD; k++) h2[k] = relu2(h2[k]);

    // ---- Layer 3: [H=10] -> [LOD=6] ----
    u64 o[LODD];
#pragma unroll
    for (int l = 0; l < LODD; l += 2) lds2(&s_b3[ns][l], o[l], o[l + 1]);
#pragma unroll
    for (int h = 0; h < HD; h++) {
#pragma unroll
        for (int l = 0; l < LODD; l += 2) {
            u64 w0, w1v; lds2(&s_w3[ns][h * LODD + l], w0, w1v);
            o[l]     = ffma2(h2[h], w0,  o[l]);
            o[l + 1] = ffma2(h2[h], w1v, o[l + 1]);
        }
    }

    // ---- Deposit into smem tile: s_out[r*25 + ns*6 + c] ----
    {
        float oa[LODD], ob[LODD];
#pragma unroll
        for (int l = 0; l < LODD; l++) unpk2(o[l], oa[l], ob[l]);
        float* pa = &s_out[r0 * 25 + ns * 6];
        float* pb = pa + 25;
#pragma unroll
        for (int l = 0; l < LODD; l++) { pa[l] = oa[l]; pb[l] = ob[l]; }
    }
    __syncthreads();

    // ---- Cooperative store: 128 rows x 96B contiguous chunks, STG.128 ----
    // Chunk base (b*722+nbase)*24B: b*722 even, nbase%4==0 -> 48k -> 16B aligned.
    const int valid_bytes = min(GN, N_NET - nbase) * 24;   // 96 or 48 (722%4==2)
#pragma unroll
    for (int u = tid; u < ROWS * 6; u += 256) {
        int r = u / 6, s = u - r * 6;
        if (s * 16 < valid_bytes) {
            const float* src = &s_out[r * 25 + s * 4];
            float4 v = make_float4(src[0], src[1], src[2], src[3]);
            float* dst = out + ((size_t)(bbase + r) * N_NET + nbase) * LODD + s * 4;
            *reinterpret_cast<float4*>(dst) = v;
        }
    }
}

extern "C" void kernel_launch(void* const* d_in, const int* in_sizes, int n_in,
                              void* d_out, int out_size) {
    const float* prior = (const float*)d_in[0];
    const float* cam   = (const float*)d_in[1];
    const float* W1    = (const float*)d_in[2];
    const float* b1    = (const float*)d_in[3];
    const float* W2    = (const float*)d_in[4];
    const float* b2    = (const float*)d_in[5];
    const float* W3    = (const float*)d_in[6];
    const float* b3    = (const float*)d_in[7];
    float* out = (float*)d_out;

    dim3 grid((N_NET + GN - 1) / GN, B_TOT / ROWS);   // 181 x 64
    mlp_kernel<<<grid, 256>>>(prior, cam, W1, b1, W2, b2, W3, b3, out);
}